// round 1
// baseline (speedup 1.0000x reference)
#include <cuda_runtime.h>
#include <cstdint>

#define PI_F 3.14159265358979323846f          /* rounds to 3.1415927f, matches f32(np.pi) */
#define ANG_THR 0.08726646259971647f          /* radians(5.0) */
#define EMAX 8192
#define PMAX ((EMAX*(EMAX-1))/2)              /* 33,550,336 worst-case pairs */

// -------------------- device scratch (static: no allocation allowed) --------
__device__ float g_ang[EMAX], g_nx[EMAX], g_ny[EMAX], g_off[EMAX], g_mx[EMAX], g_my[EMAX];
__device__ float g_vals[PMAX];                 // compacted masked distances
__device__ unsigned int g_count;               // n_pairs
__device__ unsigned int g_hist[3][256];        // radix-select histograms (q1, mu, q3)
__device__ unsigned int g_pref[3];             // resolved high bits per target
__device__ unsigned int g_rank[3];             // remaining rank per target
__device__ float g_mu, g_margin;
__device__ float g_partial[2048];              // per-block loss partial sums

// shared math so K_compact / K_final produce bit-identical distances
__device__ __forceinline__ bool pair_ok(float ai, float aj) {
    float df = fabsf(aj - ai);
    df = fminf(df, PI_F - df);
    return df < ANG_THR;
}
__device__ __forceinline__ float pair_dist(float nx, float ny, float off, float mx, float my) {
    return fabsf(nx * mx + ny * my - off);
}

// -------------------- K1: per-edge geometry ---------------------------------
__global__ void k_edges(const float* __restrict__ pos, const int* __restrict__ eidx, int E) {
    int idx = blockIdx.x * blockDim.x + threadIdx.x;
    if (idx >= E) return;
    int s = eidx[idx];
    int d = eidx[E + idx];
    float sx = pos[2 * s], sy = pos[2 * s + 1];
    float dx = pos[2 * d], dy = pos[2 * d + 1];
    float ddx = dx - sx, ddy = dy - sy;
    float len = fmaxf(sqrtf(ddx * ddx + ddy * ddy), 1e-8f);
    float ux = ddx / len, uy = ddy / len;
    float a = atan2f(uy, ux);
    a = fmodf(a, PI_F);
    if (a < 0.f) a += PI_F;
    g_ang[idx] = a;
    g_nx[idx] = -uy;
    g_ny[idx] = ux;
    g_off[idx] = sx * (-uy) + sy * ux;
    g_mx[idx] = (sx + dx) * 0.5f;
    g_my[idx] = (sy + dy) * 0.5f;
}

// -------------------- K2: reset state (every launch — graph replay!) --------
__global__ void k_init() {
    int tid = threadIdx.x;
    unsigned* h = (unsigned*)g_hist;
    for (int t = tid; t < 768; t += 256) h[t] = 0;
    if (tid == 0) g_count = 0;
}

// -------------------- K3: compact masked distances --------------------------
// grid (E/256, E/256), 256 threads. Block staging buffer -> ~1 global atomic
// per 2048 values (same-address L2 atomics would otherwise dominate).
__global__ void k_compact(int E) {
    __shared__ float s_a[256], s_nx[256], s_ny[256], s_off[256];
    __shared__ float s_buf[2048];
    __shared__ unsigned s_cnt, s_base;

    int jb = blockIdx.x * 256;
    int i0 = blockIdx.y * 256;
    if (jb + 255 <= i0) return;                 // entire tile has j <= i

    int tid = threadIdx.x;
    int j = jb + tid;
    if (tid == 0) s_cnt = 0;
    int ii = i0 + tid;
    s_a[tid]   = g_ang[ii];
    s_nx[tid]  = g_nx[ii];
    s_ny[tid]  = g_ny[ii];
    s_off[tid] = g_off[ii];
    __syncthreads();

    float aj = g_ang[j], mxj = g_mx[j], myj = g_my[j];
    int lane = tid & 31;

    for (int k = 0; k < 256; k++) {
        int i = i0 + k;
        bool valid = false;
        float dist = 0.f;
        if (j > i && pair_ok(s_a[k], aj)) {
            dist = pair_dist(s_nx[k], s_ny[k], s_off[k], mxj, myj);
            valid = true;
        }
        unsigned bal = __ballot_sync(0xffffffffu, valid);
        if (bal) {
            int leader = __ffs(bal) - 1;
            unsigned base = 0;
            if (lane == leader) base = atomicAdd(&s_cnt, (unsigned)__popc(bal));
            base = __shfl_sync(0xffffffffu, base, leader);
            if (valid) {
                int posn = __popc(bal & ((1u << lane) - 1u));
                s_buf[base + posn] = dist;
            }
        }
        __syncthreads();
        if (s_cnt >= 2048u - 256u) {
            if (tid == 0) s_base = atomicAdd(&g_count, s_cnt);
            __syncthreads();
            for (unsigned t = tid; t < s_cnt; t += 256) g_vals[s_base + t] = s_buf[t];
            __syncthreads();
            if (tid == 0) s_cnt = 0;
            __syncthreads();
        }
    }
    if (s_cnt) {
        if (tid == 0) s_base = atomicAdd(&g_count, s_cnt);
        __syncthreads();
        for (unsigned t = tid; t < s_cnt; t += 256) g_vals[s_base + t] = s_buf[t];
    }
}

// -------------------- K4: initialize ranks from n_pairs ---------------------
__global__ void k_ranks() {
    if (threadIdx.x == 0) {
        unsigned n = g_count;
        unsigned k1 = 0, kmu = 0, k3 = 0;
        if (n > 0) {
            unsigned q = n / 4u;
            k1 = (q >= 1u) ? q - 1u : 0u;       // max(0, n//4 - 1)
            kmu = n / 2u;                       // n//2
            unsigned a = (3u * n) / 4u;         // min(n-1, 3n//4)
            k3 = (a < n - 1u) ? a : (n - 1u);
        }
        g_rank[0] = k1; g_rank[1] = kmu; g_rank[2] = k3;
        g_pref[0] = 0;  g_pref[1] = 0;   g_pref[2] = 0;
    }
}

// -------------------- K5: radix-select histogram pass -----------------------
// Non-negative floats: uint bit pattern is order-preserving.
__global__ void k_hist(int p) {
    __shared__ unsigned sh[768];
    int tid = threadIdx.x;
    for (int t = tid; t < 768; t += blockDim.x) sh[t] = 0;
    __syncthreads();

    unsigned n = g_count;
    int shift = 24 - 8 * p;
    unsigned p0 = g_pref[0], p1 = g_pref[1], p2 = g_pref[2];
    unsigned long long hs = (unsigned long long)(shift + 8);

    for (unsigned idx = blockIdx.x * blockDim.x + tid; idx < n;
         idx += gridDim.x * blockDim.x) {
        unsigned u = __float_as_uint(g_vals[idx]);
        unsigned dig = (u >> shift) & 255u;
        bool m0, m1, m2;
        if (p == 0) { m0 = m1 = m2 = true; }
        else {
            m0 = (((unsigned long long)(u ^ p0)) >> hs) == 0ull;
            m1 = (((unsigned long long)(u ^ p1)) >> hs) == 0ull;
            m2 = (((unsigned long long)(u ^ p2)) >> hs) == 0ull;
        }
        if (m0) atomicAdd(&sh[dig], 1u);
        if (m1) atomicAdd(&sh[256 + dig], 1u);
        if (m2) atomicAdd(&sh[512 + dig], 1u);
    }
    __syncthreads();
    unsigned* h = (unsigned*)g_hist;
    for (int t = tid; t < 768; t += blockDim.x) {
        unsigned v = sh[t];
        if (v) atomicAdd(&h[t], v);
    }
}

// -------------------- K6: resolve one radix digit ----------------------------
__global__ void k_resolve(int p) {
    __shared__ unsigned s_h[3][256];
    int tid = threadIdx.x;                      // 256 threads
    for (int t = 0; t < 3; t++) s_h[t][tid] = g_hist[t][tid];
    __syncthreads();

    if (tid < 3) {
        int t = tid;
        unsigned rank = g_rank[t];
        unsigned cum = 0;
        int shift = 24 - 8 * p;
        unsigned sel = 255u;
        for (int b = 0; b < 256; b++) {
            unsigned c = s_h[t][b];
            if (cum + c > rank) { sel = (unsigned)b; break; }
            cum += c;
        }
        g_pref[t] |= sel << shift;
        g_rank[t] = rank - cum;
    }
    __syncthreads();
    for (int t = 0; t < 3; t++) g_hist[t][tid] = 0;   // ready for next pass

    if (p == 3 && tid == 0) {
        unsigned n = g_count;
        if (n == 0) { g_mu = 0.f; g_margin = 0.f; }
        else {
            float q1 = __uint_as_float(g_pref[0]);
            float mu = __uint_as_float(g_pref[1]);
            float q3 = __uint_as_float(g_pref[2]);
            g_mu = mu;
            g_margin = fmaxf(q3 - q1, 1e-6f) * 0.75f;   // iqr*0.5*1.5
        }
    }
}

// -------------------- K7: final pass — write outputs, partial loss sums -----
// Output layout: d_out[0]=loss, [1,1+EE)=mask(f32 0/1), [1+EE,1+2EE)=per_pair_loss,
// [1+2EE]=weight. Regions start at +1 float => float4 stores must target j≡3 mod 4.
__global__ void k_final(float* __restrict__ dout, int E) {
    const int IB = 64;
    __shared__ float s_a[IB], s_nx[IB], s_ny[IB], s_off[IB];
    __shared__ float s_red[256];

    int tid = threadIdx.x;
    int tg = blockIdx.x * 256 + tid;            // 0..2047 (E/4 groups)
    int i0 = blockIdx.y * IB;

    if (tid < IB) {
        int ii = i0 + tid;
        s_a[tid] = g_ang[ii]; s_nx[tid] = g_nx[ii];
        s_ny[tid] = g_ny[ii]; s_off[tid] = g_off[ii];
    }
    __syncthreads();

    bool special = (tg == (E / 4) - 1);         // last group handles j=0,1,2,E-1
    int j[4];
    if (special) { j[0] = 0; j[1] = 1; j[2] = 2; j[3] = E - 1; }
    else { j[0] = 3 + 4 * tg; j[1] = j[0] + 1; j[2] = j[0] + 2; j[3] = j[0] + 3; }

    float aj[4], mxj[4], myj[4];
#pragma unroll
    for (int q = 0; q < 4; q++) { aj[q] = g_ang[j[q]]; mxj[q] = g_mx[j[q]]; myj[q] = g_my[j[q]]; }

    float mu = g_mu, mg = g_margin;
    size_t EE = (size_t)E * (size_t)E;
    float* omask = dout + 1;
    float* oloss = dout + 1 + EE;
    float lsum = 0.f;

    for (int k = 0; k < IB; k++) {
        int i = i0 + k;
        float ai = s_a[k], nx = s_nx[k], ny = s_ny[k], off = s_off[k];
        float lv[4], mv[4];
#pragma unroll
        for (int q = 0; q < 4; q++) {
            float l = 0.f, m = 0.f;
            if (j[q] > i && pair_ok(ai, aj[q])) {
                float d = pair_dist(nx, ny, off, mxj[q], myj[q]);
                l = fmaxf(fabsf(d - mu) - mg, 0.f);
                m = (l > 0.f) ? 1.f : 0.f;
            }
            lv[q] = l; mv[q] = m; lsum += l;
        }
        size_t rbase = (size_t)i * (size_t)E;
        if (!special) {
            size_t o = rbase + (size_t)j[0];
            *(float4*)(omask + o) = make_float4(mv[0], mv[1], mv[2], mv[3]);
            *(float4*)(oloss + o) = make_float4(lv[0], lv[1], lv[2], lv[3]);
        } else {
#pragma unroll
            for (int q = 0; q < 4; q++) {
                omask[rbase + (size_t)j[q]] = mv[q];
                oloss[rbase + (size_t)j[q]] = lv[q];
            }
        }
    }

    // deterministic block reduction into fixed partial slot
    s_red[tid] = lsum;
    __syncthreads();
    for (int o = 128; o > 0; o >>= 1) {
        if (tid < o) s_red[tid] += s_red[tid + o];
        __syncthreads();
    }
    if (tid == 0) g_partial[blockIdx.y * gridDim.x + blockIdx.x] = s_red[0];
}

// -------------------- K8: final deterministic reduction + scalars -----------
__global__ void k_reduce(float* __restrict__ dout, const float* __restrict__ weight,
                         long long out_size, int npart) {
    __shared__ float s[1024];
    int tid = threadIdx.x;
    float v = 0.f;
    for (int t = tid; t < npart; t += 1024) v += g_partial[t];
    s[tid] = v;
    __syncthreads();
    for (int o = 512; o > 0; o >>= 1) {
        if (tid < o) s[tid] += s[tid + o];
        __syncthreads();
    }
    if (tid == 0) {
        unsigned n = g_count;
        float denom = (n > 1u) ? (float)n : 1.0f;
        dout[0] = s[0] / denom;
        dout[out_size - 1] = weight[0];
    }
}

// ============================================================================
extern "C" void kernel_launch(void* const* d_in, const int* in_sizes, int n_in,
                              void* d_out, int out_size) {
    const float* pos    = (const float*)d_in[0];
    // d_in[1] = adjacency: unused by the reference computation
    const int*   eidx   = (const int*)d_in[2];
    const float* weight = (const float*)d_in[3];
    int E = in_sizes[2] / 2;                    // 8192
    float* out = (float*)d_out;

    k_edges<<<(E + 255) / 256, 256>>>(pos, eidx, E);
    k_init<<<1, 256>>>();

    dim3 gc(E / 256, E / 256);                  // 32 x 32
    k_compact<<<gc, 256>>>(E);
    k_ranks<<<1, 32>>>();

    for (int p = 0; p < 4; p++) {
        k_hist<<<1024, 256>>>(p);
        k_resolve<<<1, 256>>>(p);
    }

    dim3 gf(E / 1024, E / 64);                  // 8 x 128 = 1024 blocks
    k_final<<<gf, 256>>>(out, E);
    k_reduce<<<1, 1024>>>(out, weight, (long long)out_size, gf.x * gf.y);
}